// round 12
// baseline (speedup 1.0000x reference)
#include <cuda_runtime.h>
#include <math.h>

#define G_      256
#define NATOMS  32
#define DD      41
#define NRAD    4
#define NCOEF   16
#define NOUT    64
#define TPB     128
#define BPA     18
#define QPL     11                                 // quads per line (ceil 41/4)
#define NQUADS  (DD * DD * QPL)                    // 18491
#define NTILES  ((NQUADS + TPB - 1) / TPB)         // 145

typedef unsigned long long u64;

__device__ float g_scratch[NATOMS][BPA][NOUT];
__device__ int   g_cnt[NATOMS];                    // zero-init; self-resetting

__device__ __forceinline__ u64 pack2(float lo, float hi) {
    u64 r; asm("mov.b64 %0, {%1,%2};" : "=l"(r) : "f"(lo), "f"(hi)); return r;
}
__device__ __forceinline__ void unpack2(u64 p, float& lo, float& hi) {
    asm("mov.b64 {%0,%1}, %2;" : "=f"(lo), "=f"(hi) : "l"(p));
}
__device__ __forceinline__ void fma2(u64& d, u64 a, u64 b) {
    asm("fma.rn.f32x2 %0, %1, %2, %0;" : "+l"(d) : "l"(a), "l"(b));
}
__device__ __forceinline__ u64 add2(u64 a, u64 b) {
    u64 r; asm("add.rn.f32x2 %0, %1, %2;" : "=l"(r) : "l"(a), "l"(b)); return r;
}

__launch_bounds__(TPB, 4)
__global__ void project_kernel(const float* __restrict__ rho,
                               const float* __restrict__ positions,
                               const float* __restrict__ Wmat,
                               const int*   __restrict__ offs,
                               float*       __restrict__ out)
{
    const int atom = blockIdx.x / BPA;
    const int ub   = blockIdx.x % BPA;
    const int t    = threadIdx.x;

    __shared__ float red[NOUT];
    __shared__ float part[2][NOUT];
    __shared__ int   lastFlag;
    if (t < NOUT) red[t] = 0.0f;
    __syncthreads();

    // per-atom uniform setup (registers only; no tables)
    const float Af = 0.1f;
    float px = __ldg(positions + atom * 3 + 0);
    float py = __ldg(positions + atom * 3 + 1);
    float pz = __ldg(positions + atom * 3 + 2);
    float cmfx = rintf(px / Af), cmfy = rintf(py / Af), cmfz = rintf(pz / Af);
    float drx = px - Af * cmfx, dry = py - Af * cmfy, drz = pz - Af * cmfz;
    int cmx = (int)cmfx, cmy = (int)cmfy, cmz = (int)cmfz;

    u64 acc2[NRAD][NCOEF / 2];
    #pragma unroll
    for (int a = 0; a < NRAD; a++)
        #pragma unroll
        for (int h = 0; h < NCOEF / 2; h++) acc2[a][h] = 0ull;

    // stage: decode quad + issue 4 independent LDGs (unconditional)
    auto stage = [&](int tile, float* sr, float& sX, float& sY, float& sz0) {
        int qq = tile * TPB + t;
        if (qq >= NQUADS) qq = 0;                  // corner quad: always out-of-sphere
        int i   = qq / (DD * QPL);
        int rem = qq - i * (DD * QPL);
        int j   = rem / QPL;
        int qk  = rem - j * QPL;
        int k0  = qk * 4;
        sX  = Af * (float)(i - 20) - drx;
        sY  = Af * (float)(j - 20) - dry;
        sz0 = (float)(k0 - 20);
        int ixy = (((cmx + i - 20) & 255) << 16) | (((cmy + j - 20) & 255) << 8);
        int kz  = cmz + k0 - 20;
        #pragma unroll
        for (int u = 0; u < 4; u++)
            sr[u] = __ldg(rho + (ixy | ((kz + u) & 255)));
    };

    auto compute = [&](const float* sr, float X, float Y, float z0) {
        float rho2 = fmaf(X, X, Y * Y);
        if (__all_sync(0xffffffffu, rho2 >= 4.0f)) return;   // whole-warp reject
        #pragma unroll
        for (int u = 0; u < 4; u++) {
            float Z = Af * (z0 + (float)u) - drz;
            float r2 = fmaf(Z, Z, rho2);
            float srho = (r2 < 4.0f) ? sr[u] : 0.0f;   // exact: dead lanes add 0
            if (!__any_sync(0xffffffffu, srho != 0.0f)) continue;

            float rinv = (r2 > 1e-30f) ? rsqrtf(r2) : 0.0f;
            float R = r2 * rinv;
            float tt = 2.0f - R;
            float g0 = r2 * tt * tt;
            float g1 = g0 * tt, g2 = g1 * tt, g3 = g2 * tt;

            float u_ = X * rinv, v_ = Y * rinv, w_ = Z * rinv;
            float u2 = u_ * u_, v2 = v_ * v_, w2 = w_ * w_;
            float uv = u_ * v_;
            float f5w1 = fmaf(5.0f, w2, -1.0f);
            float umv = u2 - v2;

            float Yv[NCOEF];
            Yv[0]  = 0.28209479177387814f;
            Yv[1]  = 0.48860251190291992f * v_;
            Yv[2]  = 0.48860251190291992f * w_;
            Yv[3]  = 0.48860251190291992f * u_;
            Yv[4]  = 1.09254843059207907f * uv;
            Yv[5]  = 1.09254843059207907f * (v_ * w_);
            Yv[6]  = 0.31539156525252005f * fmaf(3.0f, w2, -1.0f);
            Yv[7]  = 1.09254843059207907f * (u_ * w_);
            Yv[8]  = 0.54627421529603959f * umv;
            Yv[9]  = 0.59004358992664352f * (v_ * fmaf(3.0f, u2, -v2));
            Yv[10] = 2.89061144264055405f * (uv * w_);
            Yv[11] = 0.45704579946446577f * (v_ * f5w1);
            Yv[12] = 0.37317633259011546f * (w_ * fmaf(5.0f, w2, -3.0f));
            Yv[13] = 0.45704579946446577f * (u_ * f5w1);
            Yv[14] = 1.44530572132027735f * (w_ * umv);
            Yv[15] = 0.59004358992664352f * (u_ * fmaf(u2, 1.0f, -3.0f * v2));

            u64 Ypk[NCOEF / 2];
            #pragma unroll
            for (int hh = 0; hh < NCOEF / 2; hh++)
                Ypk[hh] = pack2(Yv[2 * hh], Yv[2 * hh + 1]);

            float gr0 = g0 * srho, gr1 = g1 * srho;
            float gr2 = g2 * srho, gr3 = g3 * srho;
            u64 gp0 = pack2(gr0, gr0), gp1 = pack2(gr1, gr1);
            u64 gp2 = pack2(gr2, gr2), gp3 = pack2(gr3, gr3);

            #pragma unroll
            for (int hh = 0; hh < NCOEF / 2; hh++) {
                fma2(acc2[0][hh], gp0, Ypk[hh]);
                fma2(acc2[1][hh], gp1, Ypk[hh]);
                fma2(acc2[2][hh], gp2, Ypk[hh]);
                fma2(acc2[3][hh], gp3, Ypk[hh]);
            }
        }
    };

    // double-buffered tile loop: ping-pong register sets, loads 1 tile ahead
    float srA[4], srB[4];
    float XA, YA, zA, XB, YB, zB;
    if (ub < NTILES) stage(ub, srA, XA, YA, zA);
    #pragma unroll 1
    for (int tile = ub; tile < NTILES; tile += 2 * BPA) {
        int tB = tile + BPA;
        if (tB < NTILES) stage(tB, srB, XB, YB, zB);   // in flight over compute A
        compute(srA, XA, YA, zA);
        int tA = tile + 2 * BPA;
        if (tA < NTILES) stage(tA, srA, XA, YA, zA);   // in flight over compute B
        if (tB < NTILES) compute(srB, XB, YB, zB);
    }

    // Block reduction: packed warp butterfly -> shared atomics
    #pragma unroll
    for (int a = 0; a < NRAD; a++) {
        #pragma unroll
        for (int h = 0; h < NCOEF / 2; h++) {
            u64 v = acc2[a][h];
            #pragma unroll
            for (int o = 16; o > 0; o >>= 1)
                v = add2(v, __shfl_down_sync(0xffffffffu, v, o));
            if ((t & 31) == 0) {
                float lo, hi;
                unpack2(v, lo, hi);
                atomicAdd(&red[a * NCOEF + 2 * h],     lo);
                atomicAdd(&red[a * NCOEF + 2 * h + 1], hi);
            }
        }
    }
    __syncthreads();

    // Publish partial, then elect last block (write -> fence -> SYNC -> atomic).
    if (t < NOUT) g_scratch[atom][ub][t] = red[t];
    __threadfence();
    __syncthreads();
    if (t == 0) {
        int c = atomicAdd(&g_cnt[atom], 1);
        lastFlag = (c == BPA - 1);
    }
    __syncthreads();
    if (lastFlag) {
        __threadfence();
        // Parallel partial reduce: 2 threads per column, loads batched.
        int col  = t & 63;
        int half = t >> 6;                         // 0 or 1
        float s = 0.0f;
        #pragma unroll
        for (int b = 0; b < BPA; b += 2) {
            int bb = b + half;
            if (bb < BPA) s += g_scratch[atom][bb][col];
        }
        part[half][col] = s;
        __syncthreads();
        if (t < NOUT) {
            int n = t >> 4, c = t & 15;
            const double dens[4]  = {1474560.0, 5898240.0, 23592960.0, 94371840.0};
            const double prods[4] = {1663200.0, 8648640.0, 32432400.0, 98017920.0};
            const double Ad = 25.6 / 256.0;
            const float vcell = (float)(Ad * Ad * Ad);
            float mt[NRAD];
            #pragma unroll
            for (int a = 0; a < NRAD; a++)
                mt[a] = part[0][a * NCOEF + c] + part[1][a * NCOEF + c];
            float sum = 0.0f;
            #pragma unroll
            for (int a = 0; a < NRAD; a++) {
                float invNn = (float)sqrt(prods[a] / dens[a]);
                sum += __ldg(Wmat + n * 4 + a) * invNn * mt[a];
            }
            out[atom * NOUT + t] = sum * vcell;
        }
        if (t == 0) g_cnt[atom] = 0;               // reset for next graph replay
    }
}

extern "C" void kernel_launch(void* const* d_in, const int* in_sizes, int n_in,
                              void* d_out, int out_size) {
    const float* rho  = (const float*)d_in[0];
    const float* pos  = (const float*)d_in[1];
    const float* W    = (const float*)d_in[2];
    const int*   offs = (const int*)d_in[3];
    float* out = (float*)d_out;

    project_kernel<<<NATOMS * BPA, TPB>>>(rho, pos, W, offs, out);
}

// round 13
// speedup vs baseline: 1.0326x; 1.0326x over previous
#include <cuda_runtime.h>
#include <math.h>

#define G_      256
#define NATOMS  32
#define DD      41
#define NRAD    4
#define NCOEF   16
#define NOUT    64
#define TPB     128
#define BPA     23
#define QPL     11                                 // aligned quads per line
#define NQUADS  (DD * DD * QPL)                    // 18491
#define NTILES  ((NQUADS + TPB - 1) / TPB)         // 145

typedef unsigned long long u64;

__device__ float g_scratch[NATOMS][BPA][NOUT];
__device__ int   g_cnt[NATOMS];                    // zero-init; self-resetting

__device__ __forceinline__ u64 pack2(float lo, float hi) {
    u64 r; asm("mov.b64 %0, {%1,%2};" : "=l"(r) : "f"(lo), "f"(hi)); return r;
}
__device__ __forceinline__ void unpack2(u64 p, float& lo, float& hi) {
    asm("mov.b64 {%0,%1}, %2;" : "=f"(lo), "=f"(hi) : "l"(p));
}
__device__ __forceinline__ void fma2(u64& d, u64 a, u64 b) {
    asm("fma.rn.f32x2 %0, %1, %2, %0;" : "+l"(d) : "l"(a), "l"(b));
}
__device__ __forceinline__ u64 add2(u64 a, u64 b) {
    u64 r; asm("add.rn.f32x2 %0, %1, %2;" : "=l"(r) : "l"(a), "l"(b)); return r;
}

__launch_bounds__(TPB, 5)
__global__ void project_kernel(const float* __restrict__ rho,
                               const float* __restrict__ positions,
                               const float* __restrict__ Wmat,
                               const int*   __restrict__ offs,
                               float*       __restrict__ out)
{
    const int atom = blockIdx.x / BPA;
    const int ub   = blockIdx.x % BPA;
    const int t    = threadIdx.x;

    __shared__ float red[NOUT];
    __shared__ float part[2][NOUT];
    __shared__ int   lastFlag;
    if (t < NOUT) red[t] = 0.0f;
    __syncthreads();

    // per-atom uniform setup (registers only; no tables)
    const float Af = 0.1f;
    float px = __ldg(positions + atom * 3 + 0);
    float py = __ldg(positions + atom * 3 + 1);
    float pz = __ldg(positions + atom * 3 + 2);
    float cmfx = rintf(px / Af), cmfy = rintf(py / Af), cmfz = rintf(pz / Af);
    float drx = px - Af * cmfx, dry = py - Af * cmfy, drz = pz - Af * cmfz;
    int cmx = (int)cmfx, cmy = (int)cmfy, cmz = (int)cmfz;
    const int qb0 = (cmz - 20) >> 2;               // aligned quad base (floor div)

    u64 acc2[NRAD][NCOEF / 2];
    #pragma unroll
    for (int a = 0; a < NRAD; a++)
        #pragma unroll
        for (int h = 0; h < NCOEF / 2; h++) acc2[a][h] = 0ull;

    for (int tile = ub; tile < NTILES; tile += BPA) {
        int qq = tile * TPB + t;
        if (qq >= NQUADS) qq = 0;                  // corner quad: circle-rejected / masked

        int i   = qq / (DD * QPL);
        int rem = qq - i * (DD * QPL);
        int j   = rem / QPL;
        int qk  = rem - j * QPL;
        int zb  = (qb0 + qk) * 4;                  // absolute 4-aligned z index

        float X = Af * (float)(i - 20) - drx;
        float Y = Af * (float)(j - 20) - dry;
        float rho2 = fmaf(X, X, Y * Y);

        // whole-warp circle rejection: no loads, no body
        if (__all_sync(0xffffffffu, rho2 >= 4.0f)) continue;

        int ixy = (((cmx + i - 20) & 255) << 16) | (((cmy + j - 20) & 255) << 8);
        int addr = ixy | (zb & 255);               // zb mult of 4 -> 16B aligned, no wrap inside
        float4 rv = __ldg((const float4*)(rho + addr));   // one LDG.128 per quad
        float sr[4] = {rv.x, rv.y, rv.z, rv.w};
        int zi = zb - cmz;                          // Z = Af*(zi+u) - drz

        #pragma unroll
        for (int u = 0; u < 4; u++) {
            float Z = Af * (float)(zi + u) - drz;
            float r2 = fmaf(Z, Z, rho2);
            float srho = (r2 < 4.0f) ? sr[u] : 0.0f;   // exact: dead/overshoot adds 0
            if (!__any_sync(0xffffffffu, srho != 0.0f)) continue;

            float rinv = (r2 > 1e-30f) ? rsqrtf(r2) : 0.0f;
            float R = r2 * rinv;
            float tt = 2.0f - R;
            float g0 = r2 * tt * tt;
            float g1 = g0 * tt, g2 = g1 * tt, g3 = g2 * tt;

            float u_ = X * rinv, v_ = Y * rinv, w_ = Z * rinv;
            float u2 = u_ * u_, v2 = v_ * v_, w2 = w_ * w_;
            float uv = u_ * v_;
            float f5w1 = fmaf(5.0f, w2, -1.0f);
            float umv = u2 - v2;

            // RAW polynomials (SH constants folded into the final mix)
            float P[NCOEF];
            P[0]  = 1.0f;
            P[1]  = v_;
            P[2]  = w_;
            P[3]  = u_;
            P[4]  = uv;
            P[5]  = v_ * w_;
            P[6]  = fmaf(3.0f, w2, -1.0f);
            P[7]  = u_ * w_;
            P[8]  = umv;
            P[9]  = v_ * fmaf(3.0f, u2, -v2);
            P[10] = uv * w_;
            P[11] = v_ * f5w1;
            P[12] = w_ * fmaf(5.0f, w2, -3.0f);
            P[13] = u_ * f5w1;
            P[14] = w_ * umv;
            P[15] = u_ * fmaf(u2, 1.0f, -3.0f * v2);

            u64 Ppk[NCOEF / 2];
            #pragma unroll
            for (int hh = 0; hh < NCOEF / 2; hh++)
                Ppk[hh] = pack2(P[2 * hh], P[2 * hh + 1]);

            float gr0 = g0 * srho, gr1 = g1 * srho;
            float gr2 = g2 * srho, gr3 = g3 * srho;
            u64 gp0 = pack2(gr0, gr0), gp1 = pack2(gr1, gr1);
            u64 gp2 = pack2(gr2, gr2), gp3 = pack2(gr3, gr3);

            #pragma unroll
            for (int hh = 0; hh < NCOEF / 2; hh++) {
                fma2(acc2[0][hh], gp0, Ppk[hh]);
                fma2(acc2[1][hh], gp1, Ppk[hh]);
                fma2(acc2[2][hh], gp2, Ppk[hh]);
                fma2(acc2[3][hh], gp3, Ppk[hh]);
            }
        }
    }

    // Block reduction: packed warp butterfly -> shared atomics
    #pragma unroll
    for (int a = 0; a < NRAD; a++) {
        #pragma unroll
        for (int h = 0; h < NCOEF / 2; h++) {
            u64 v = acc2[a][h];
            #pragma unroll
            for (int o = 16; o > 0; o >>= 1)
                v = add2(v, __shfl_down_sync(0xffffffffu, v, o));
            if ((t & 31) == 0) {
                float lo, hi;
                unpack2(v, lo, hi);
                atomicAdd(&red[a * NCOEF + 2 * h],     lo);
                atomicAdd(&red[a * NCOEF + 2 * h + 1], hi);
            }
        }
    }
    __syncthreads();

    // Publish partial, then elect last block (write -> fence -> SYNC -> atomic).
    if (t < NOUT) g_scratch[atom][ub][t] = red[t];
    __threadfence();
    __syncthreads();
    if (t == 0) {
        int c = atomicAdd(&g_cnt[atom], 1);
        lastFlag = (c == BPA - 1);
    }
    __syncthreads();
    if (lastFlag) {
        __threadfence();
        // Parallel partial reduce: 2 threads per column, loads batched.
        int col  = t & 63;
        int half = t >> 6;
        float s = 0.0f;
        #pragma unroll
        for (int b = 0; b < BPA; b += 2) {
            int bb = b + half;
            if (bb < BPA) s += g_scratch[atom][bb][col];
        }
        part[half][col] = s;
        __syncthreads();
        if (t < NOUT) {
            int n = t >> 4, c = t & 15;
            const float Cc[NCOEF] = {                      // folded SH constants
                0.28209479177387814f, 0.48860251190291992f, 0.48860251190291992f,
                0.48860251190291992f, 1.09254843059207907f, 1.09254843059207907f,
                0.31539156525252005f, 1.09254843059207907f, 0.54627421529603959f,
                0.59004358992664352f, 2.89061144264055405f, 0.45704579946446577f,
                0.37317633259011546f, 0.45704579946446577f, 1.44530572132027735f,
                0.59004358992664352f };
            const double dens[4]  = {1474560.0, 5898240.0, 23592960.0, 94371840.0};
            const double prods[4] = {1663200.0, 8648640.0, 32432400.0, 98017920.0};
            const double Ad = 25.6 / 256.0;
            const float vcell = (float)(Ad * Ad * Ad);
            float mt[NRAD];
            #pragma unroll
            for (int a = 0; a < NRAD; a++)
                mt[a] = part[0][a * NCOEF + c] + part[1][a * NCOEF + c];
            float sum = 0.0f;
            #pragma unroll
            for (int a = 0; a < NRAD; a++) {
                float invNn = (float)sqrt(prods[a] / dens[a]);
                sum += __ldg(Wmat + n * 4 + a) * invNn * mt[a];
            }
            out[atom * NOUT + t] = sum * (Cc[c] * vcell);
        }
        if (t == 0) g_cnt[atom] = 0;               // reset for next graph replay
    }
}

extern "C" void kernel_launch(void* const* d_in, const int* in_sizes, int n_in,
                              void* d_out, int out_size) {
    const float* rho  = (const float*)d_in[0];
    const float* pos  = (const float*)d_in[1];
    const float* W    = (const float*)d_in[2];
    const int*   offs = (const int*)d_in[3];
    float* out = (float*)d_out;

    project_kernel<<<NATOMS * BPA, TPB>>>(rho, pos, W, offs, out);
}